// round 16
// baseline (speedup 1.0000x reference)
#include <cuda_runtime.h>
#include <cuda_fp16.h>

#define HH 256
#define WW 256
#define KK 64
#define MV 16
#define NSTEPS 64
#define VOLR 256.0f
#define DTST (1.0f/256.0f)

// Template quad-cell entries IN PERMUTED AXES, u8-quantized:
// entry [k][z'][y'][x'] = uint4 { cell(x,y), cell(x+1,y), cell(x,y+1), cell(x+1,y+1) }
// each cell = 4xu8 (r,g,b,a), value = round(v*255). 4 MB.
// A trilinear fetch = 2 LDG.128 (planes z0 and z0+1).
__device__ uint4 g_tmpl[KK * MV * MV * MV];
// Per-prim params (permuted to match): 4 float4 per prim.
__device__ float4 g_prim[KK * 4];
// Constant-memory mirror — inner loop reads warp-uniform -> LDC (off the L1 pipe).
__constant__ float4 c_prim[KK * 4];

// Dominant local axis of the (uniform) march direction d=(0,0,1).
__device__ __forceinline__ void perm_for_prim(
    const float* __restrict__ primrot, const float* __restrict__ primscale,
    int k, int& p, int& q, int& r)
{
    float a0 = fabsf(primrot[k * 9 + 6] * primscale[k * 3 + 0]);
    float a1 = fabsf(primrot[k * 9 + 7] * primscale[k * 3 + 1]);
    float a2 = fabsf(primrot[k * 9 + 8] * primscale[k * 3 + 2]);
    p = 0;
    float m = a0;
    if (a1 > m) { p = 1; m = a1; }
    if (a2 > m) { p = 2; }
    q = (p == 0) ? 1 : 0;
    r = (p == 2) ? 1 : 2;
}

__device__ __forceinline__ unsigned quant_cell(const float* base, int v) {
    unsigned r = (unsigned)(int)(base[v]          * 255.0f + 0.5f);
    unsigned g = (unsigned)(int)(base[4096 + v]   * 255.0f + 0.5f);
    unsigned b = (unsigned)(int)(base[8192 + v]   * 255.0f + 0.5f);
    unsigned a = (unsigned)(int)(base[12288 + v]  * 255.0f + 0.5f);
    return r | (g << 8) | (b << 16) | (a << 24);
}

// Blocks 0..1023: repack template to permuted quad u8. Block 1024: prep prim params.
__global__ void pack_prep_kernel(const float* __restrict__ primrgba,
                                 const float* __restrict__ primpos,
                                 const float* __restrict__ primrot,
                                 const float* __restrict__ primscale) {
    int b = blockIdx.x;
    if (b < 1024) {
        int idx = b * 256 + threadIdx.x;
        int k = idx >> 12;
        int vp = idx & 4095;          // permuted z'*256 + y'*16 + x'
        int xp = vp & 15;
        int yp = (vp >> 4) & 15;
        int zp = vp >> 8;

        int p, q, r;
        perm_for_prim(primrot, primscale, k, p, q, r);

        int x1 = (xp < 15) ? xp + 1 : xp;   // clamped neighbors (x=15/y=15
        int y1 = (yp < 15) ? yp + 1 : yp;   // entries are never fetched: x0,y0<=14)
        int c[3];
        c[r] = zp;
        c[p] = xp; c[q] = yp; int v00 = c[2] * 256 + c[1] * 16 + c[0];
        c[p] = x1; c[q] = yp; int v10 = c[2] * 256 + c[1] * 16 + c[0];
        c[p] = xp; c[q] = y1; int v01 = c[2] * 256 + c[1] * 16 + c[0];
        c[p] = x1; c[q] = y1; int v11 = c[2] * 256 + c[1] * 16 + c[0];

        const float* base = primrgba + (size_t)k * 4 * 4096;
        uint4 val;
        val.x = quant_cell(base, v00);
        val.y = quant_cell(base, v10);
        val.z = quant_cell(base, v01);
        val.w = quant_cell(base, v11);
        g_tmpl[idx] = val;
    } else {
        int k = threadIdx.x;
        if (k >= KK) return;
        int p, q, r;
        perm_for_prim(primrot, primscale, k, p, q, r);
        const float* Rm = primrot + k * 9;
        float4 A = {Rm[0 + p], Rm[0 + q], Rm[0 + r], Rm[3 + p]};
        float4 Bv = {Rm[3 + q], Rm[3 + r], Rm[6 + p], Rm[6 + q]};
        float4 Cv = {Rm[6 + r],
                     primpos[k * 3 + 0] / VOLR,
                     primpos[k * 3 + 1] / VOLR,
                     primpos[k * 3 + 2] / VOLR};
        float4 Dv = {primscale[k * 3 + p],
                     primscale[k * 3 + q],
                     primscale[k * 3 + r], 0.f};
        g_prim[k * 4 + 0] = A;
        g_prim[k * 4 + 1] = Bv;
        g_prim[k * 4 + 2] = Cv;
        g_prim[k * 4 + 3] = Dv;
    }
}

// Per-point evaluation: transform + inside test + quad u8 trilinear gather (2 loads).
// Accumulates biased values (1024 + byte) into s[]; cnt counts inside evals.
__device__ __forceinline__ void eval_prim(
    const float4 A, const float4 B, const float4 C, const float4 D, int k,
    float px, float py, float pz, float s[4], float& cnt)
{
    float rx = px - C.y, ry = py - C.z, rz = pz - C.w;
    float lx = (rx * A.x + ry * A.w + rz * B.z) * D.x;
    float ly = (rx * A.y + ry * B.x + rz * B.w) * D.y;
    float lz = (rx * A.z + ry * B.y + rz * C.x) * D.z;
    if (!(fabsf(lx) < 1.0f && fabsf(ly) < 1.0f && fabsf(lz) < 1.0f)) return;

    float gx = fminf((lx + 1.0f) * 7.5f, 14.99999f);
    float gy = fminf((ly + 1.0f) * 7.5f, 14.99999f);
    float gz = fminf((lz + 1.0f) * 7.5f, 14.99999f);
    int x0 = (int)gx;
    int y0 = (int)gy;
    int z0 = (int)gz;
    float fx = gx - (float)x0;
    float fy = gy - (float)y0;
    float fz = gz - (float)z0;

    // 2 LDG.128: each holds the 2x2 (x,y) u8 quad for one z-plane
    const uint4* T = g_tmpl + (((k * MV + z0) * MV + y0) * MV + x0);
    uint4 q0 = __ldg(T + 0);    // plane z0
    uint4 q1 = __ldg(T + 256);  // plane z0+1

    float wz0 = 1.0f - fz, wy0 = 1.0f - fy, wx0 = 1.0f - fx;
    float w000 = wz0 * wy0 * wx0, w001 = wz0 * wy0 * fx;
    float w010 = wz0 * fy * wx0,  w011 = wz0 * fy * fx;
    float w100 = fz * wy0 * wx0,  w101 = fz * wy0 * fx;
    float w110 = fz * fy * wx0,   w111 = fz * fy * fx;

    // u8 -> half-magic: PRMT builds half2 bits {0x64<<8|b, ...} = 1024+b exactly.
#define ACCC(cell, w)                                                     \
    {                                                                     \
        unsigned hrg = __byte_perm((cell), 0x64, 0x4140);                 \
        unsigned hba = __byte_perm((cell), 0x64, 0x4342);                 \
        float2 rg = __half22float2(*reinterpret_cast<const __half2*>(&hrg)); \
        float2 ba = __half22float2(*reinterpret_cast<const __half2*>(&hba)); \
        s[0] = fmaf(rg.x, (w), s[0]); s[1] = fmaf(rg.y, (w), s[1]);       \
        s[2] = fmaf(ba.x, (w), s[2]); s[3] = fmaf(ba.y, (w), s[3]);       \
    }
    ACCC(q0.x, w000) ACCC(q0.y, w001) ACCC(q0.z, w010) ACCC(q0.w, w011)
    ACCC(q1.x, w100) ACCC(q1.y, w101) ACCC(q1.z, w110) ACCC(q1.w, w111)
#undef ACCC
    cnt += 1.0f;   // weights sum to 1: bias = 1024 per eval
}

// Exact OBB slab test (cull only). Reads the GLOBAL copy (lane-divergent index).
__device__ __forceinline__ bool obb_test(
    int k,
    float ox, float oy, float oz,
    float dx, float dy, float dz,
    float tmin, float tmax)
{
    float4 A = __ldg(g_prim + k * 4 + 0);
    float4 B = __ldg(g_prim + k * 4 + 1);
    float4 C = __ldg(g_prim + k * 4 + 2);
    float4 D = __ldg(g_prim + k * 4 + 3);
    float rx = ox - C.y, ry = oy - C.z, rz = oz - C.w;
    float lo3[3], ld3[3];
    lo3[0] = (rx * A.x + ry * A.w + rz * B.z) * D.x;
    lo3[1] = (rx * A.y + ry * B.x + rz * B.w) * D.y;
    lo3[2] = (rx * A.z + ry * B.y + rz * C.x) * D.z;
    ld3[0] = (dx * A.x + dy * A.w + dz * B.z) * D.x;
    ld3[1] = (dx * A.y + dy * B.x + dz * B.w) * D.y;
    ld3[2] = (dx * A.z + dy * B.y + dz * C.x) * D.z;
    float t0 = tmin, t1 = tmax;
#pragma unroll
    for (int a = 0; a < 3; a++) {
        float lo = lo3[a], ld = ld3[a];
        if (fabsf(ld) > 1e-12f) {
            float inv = 1.0f / ld;
            float ta = (-1.0f - lo) * inv;
            float tb = ( 1.0f - lo) * inv;
            t0 = fmaxf(t0, fminf(ta, tb));
            t1 = fminf(t1, fmaxf(ta, tb));
        } else if (fabsf(lo) >= 1.0f) {
            return false;
        }
    }
    return t0 <= t1;
}

// One warp per ray; lane owns steps {lane, lane+32}. 8 consecutive rays per block.
// Rows AND column groups assigned center-out (LPT): hot central blocks launch first.
__global__ __launch_bounds__(256) void march_kernel(
    const float* __restrict__ raypos,
    const float* __restrict__ raydir,
    const float* __restrict__ tminmax,
    float* __restrict__ out)
{
    int lane = threadIdx.x & 31;
    int warpId = threadIdx.x >> 5;

    // center-out row mapping: i -> 127,128,126,129,...
    int i = blockIdx.x >> 5;          // 0..255
    int rh = i & 1;
    int roff = i >> 1;
    int row = rh ? (128 + roff) : (127 - roff);
    // center-out column-group mapping: j -> 15,16,14,17,...
    int j = blockIdx.x & 31;
    int ch = j & 1;
    int coff = j >> 1;
    int colg = ch ? (16 + coff) : (15 - coff);
    int r = row * WW + colg * 8 + warpId;

    float ox = raypos[r * 3 + 0], oy = raypos[r * 3 + 1], oz = raypos[r * 3 + 2];
    float dx = raydir[r * 3 + 0], dy = raydir[r * 3 + 1], dz = raydir[r * 3 + 2];
    float tmin = tminmax[r * 2 + 0], tmax = tminmax[r * 2 + 1];

    // Cooperative exact-OBB cull: lane tests prims {lane, lane+32}
    bool a0 = obb_test(lane,      ox, oy, oz, dx, dy, dz, tmin, tmax);
    bool a1 = obb_test(lane + 32, ox, oy, oz, dx, dy, dz, tmin, tmax);
    unsigned m0 = __ballot_sync(0xFFFFFFFFu, a0);
    unsigned m1 = __ballot_sync(0xFFFFFFFFu, a1);
    unsigned long long mask = (unsigned long long)m0 |
                              ((unsigned long long)m1 << 32);

    // Two sample points per lane: steps lane and lane+32
    float t0 = fmaf((float)lane + 0.5f,  DTST, tmin);
    float t1 = fmaf((float)lane + 32.5f, DTST, tmin);
    float p0x = fmaf(t0, dx, ox), p0y = fmaf(t0, dy, oy), p0z = fmaf(t0, dz, oz);
    float p1x = fmaf(t1, dx, ox), p1y = fmaf(t1, dy, oy), p1z = fmaf(t1, dz, oz);

    float s0[4] = {0.f, 0.f, 0.f, 0.f};
    float s1[4] = {0.f, 0.f, 0.f, 0.f};
    float cnt0 = 0.f, cnt1 = 0.f;

    while (mask) {
        int k = __ffsll(mask) - 1;   // warp-uniform
        mask &= mask - 1;
        float4 A = c_prim[k * 4 + 0];   // LDC, constant port (off L1)
        float4 B = c_prim[k * 4 + 1];
        float4 C = c_prim[k * 4 + 2];
        float4 D = c_prim[k * 4 + 3];
        eval_prim(A, B, C, D, k, p0x, p0y, p0z, s0, cnt0);
        eval_prim(A, B, C, D, k, p1x, p1y, p1z, s1, cnt1);
    }

    // Remove half-magic bias (1024 per inside eval) and u8 scale (1/255).
    const float INV255 = 1.0f / 255.0f;
    float b0 = 1024.0f * cnt0, b1 = 1024.0f * cnt1;
    float v0r = (s0[0] - b0) * INV255, v0g = (s0[1] - b0) * INV255;
    float v0b = (s0[2] - b0) * INV255, v0a = (s0[3] - b0) * INV255;
    float v1r = (s1[0] - b1) * INV255, v1g = (s1[1] - b1) * INV255;
    float v1b = (s1[2] - b1) * INV255, v1a = (s1[3] - b1) * INV255;

    // Alpha compositing via prefix sum: alpha_i = min(1, sum_{j<=i} d_j)
    float d0 = (t0 < tmax) ? v0a * DTST : 0.f;
    float d1 = (t1 < tmax) ? v1a * DTST : 0.f;

    float c0 = d0;
#pragma unroll
    for (int off2 = 1; off2 < 32; off2 <<= 1) {
        float v = __shfl_up_sync(0xFFFFFFFFu, c0, off2);
        if (lane >= off2) c0 += v;
    }
    float tot0 = __shfl_sync(0xFFFFFFFFu, c0, 31);
    float c1 = d1;
#pragma unroll
    for (int off2 = 1; off2 < 32; off2 <<= 1) {
        float v = __shfl_up_sync(0xFFFFFFFFu, c1, off2);
        if (lane >= off2) c1 += v;
    }
    float S0 = c0;            // inclusive prefix at step lane
    float S1 = tot0 + c1;     // inclusive prefix at step lane+32
    float contrib0 = fminf(1.f, S0) - fminf(1.f, S0 - d0);
    float contrib1 = fminf(1.f, S1) - fminf(1.f, S1 - d1);

    float rgbx = v0r * contrib0 + v1r * contrib1;
    float rgby = v0g * contrib0 + v1g * contrib1;
    float rgbz = v0b * contrib0 + v1b * contrib1;

#pragma unroll
    for (int off2 = 16; off2 > 0; off2 >>= 1) {
        rgbx += __shfl_xor_sync(0xFFFFFFFFu, rgbx, off2);
        rgby += __shfl_xor_sync(0xFFFFFFFFu, rgby, off2);
        rgbz += __shfl_xor_sync(0xFFFFFFFFu, rgbz, off2);
    }
    float alphaF = fminf(1.f, __shfl_sync(0xFFFFFFFFu, S1, 31));

    if (lane == 0) {
        const int HWsz = HH * WW;
        out[0 * HWsz + r] = rgbx;
        out[1 * HWsz + r] = rgby;
        out[2 * HWsz + r] = rgbz;
        out[3 * HWsz + r] = alphaF;
        out[4 * HWsz + r] = rgbx;
        out[5 * HWsz + r] = rgby;
        out[6 * HWsz + r] = rgbz;
        out[7 * HWsz + r] = alphaF;
    }
}

extern "C" void kernel_launch(void* const* d_in, const int* in_sizes, int n_in,
                              void* d_out, int out_size) {
    const float* raypos    = (const float*)d_in[0];
    const float* raydir    = (const float*)d_in[1];
    const float* tminmax   = (const float*)d_in[2];
    const float* primpos   = (const float*)d_in[3];
    const float* primrot   = (const float*)d_in[4];
    const float* primscale = (const float*)d_in[5];
    const float* primrgba  = (const float*)d_in[6];
    float* out = (float*)d_out;

    pack_prep_kernel<<<1025, 256>>>(primrgba, primpos, primrot, primscale);

    // Mirror prim params into constant memory (graph-capturable D2D copy).
    void* gp = nullptr;
    cudaGetSymbolAddress(&gp, g_prim);
    cudaMemcpyToSymbolAsync(c_prim, gp, sizeof(float4) * KK * 4, 0,
                            cudaMemcpyDeviceToDevice, 0);

    march_kernel<<<HH * WW / 8, 256>>>(raypos, raydir, tminmax, out);
}

// round 17
// speedup vs baseline: 1.1188x; 1.1188x over previous
#include <cuda_runtime.h>
#include <cuda_fp16.h>

#define HH 256
#define WW 256
#define KK 64
#define MV 16
#define NSTEPS 64
#define VOLR 256.0f
#define DTST (1.0f/256.0f)

// Template with paired x-cells IN PERMUTED AXES: entry [k][z'][y'][x'] holds
// {cell(x'), cell(x'+1)} as uint4 of 4 half2 : 4 MB.
__device__ uint4 g_tmpl[KK * MV * MV * MV];
// Per-prim params (permuted to match): 4 float4 per prim.
__device__ float4 g_prim[KK * 4];
// Constant-memory mirror — inner loop reads warp-uniform -> LDC (off the L1 pipe).
__constant__ float4 c_prim[KK * 4];

// Dominant local axis of the (uniform) march direction d=(0,0,1).
__device__ __forceinline__ void perm_for_prim(
    const float* __restrict__ primrot, const float* __restrict__ primscale,
    int k, int& p, int& q, int& r)
{
    float a0 = fabsf(primrot[k * 9 + 6] * primscale[k * 3 + 0]);
    float a1 = fabsf(primrot[k * 9 + 7] * primscale[k * 3 + 1]);
    float a2 = fabsf(primrot[k * 9 + 8] * primscale[k * 3 + 2]);
    p = 0;
    float m = a0;
    if (a1 > m) { p = 1; m = a1; }
    if (a2 > m) { p = 2; }
    q = (p == 0) ? 1 : 0;
    r = (p == 2) ? 1 : 2;
}

// Blocks 0..1023: repack template to permuted paired fp16. Block 1024: prep prim params.
__global__ void pack_prep_kernel(const float* __restrict__ primrgba,
                                 const float* __restrict__ primpos,
                                 const float* __restrict__ primrot,
                                 const float* __restrict__ primscale) {
    int b = blockIdx.x;
    if (b < 1024) {
        int idx = b * 256 + threadIdx.x;
        int k = idx >> 12;
        int vp = idx & 4095;          // permuted z'*256 + y'*16 + x'
        int xp = vp & 15;
        int yp = (vp >> 4) & 15;
        int zp = vp >> 8;

        int p, q, r;
        perm_for_prim(primrot, primscale, k, p, q, r);

        int c[3];
        c[p] = xp; c[q] = yp; c[r] = zp;
        int v0 = c[2] * 256 + c[1] * 16 + c[0];
        c[p] = (xp < 15) ? xp + 1 : xp;
        int v1 = c[2] * 256 + c[1] * 16 + c[0];

        const float* base = primrgba + (size_t)k * 4 * 4096;
        __half2 rg0 = __floats2half2_rn(base[v0], base[4096 + v0]);
        __half2 ba0 = __floats2half2_rn(base[8192 + v0], base[12288 + v0]);
        __half2 rg1 = __floats2half2_rn(base[v1], base[4096 + v1]);
        __half2 ba1 = __floats2half2_rn(base[8192 + v1], base[12288 + v1]);
        uint4 val;
        val.x = *reinterpret_cast<unsigned*>(&rg0);
        val.y = *reinterpret_cast<unsigned*>(&ba0);
        val.z = *reinterpret_cast<unsigned*>(&rg1);
        val.w = *reinterpret_cast<unsigned*>(&ba1);
        g_tmpl[idx] = val;
    } else {
        int k = threadIdx.x;
        if (k >= KK) return;
        int p, q, r;
        perm_for_prim(primrot, primscale, k, p, q, r);
        const float* Rm = primrot + k * 9;
        float4 A = {Rm[0 + p], Rm[0 + q], Rm[0 + r], Rm[3 + p]};
        float4 Bv = {Rm[3 + q], Rm[3 + r], Rm[6 + p], Rm[6 + q]};
        float4 Cv = {Rm[6 + r],
                     primpos[k * 3 + 0] / VOLR,
                     primpos[k * 3 + 1] / VOLR,
                     primpos[k * 3 + 2] / VOLR};
        float4 Dv = {primscale[k * 3 + p],
                     primscale[k * 3 + q],
                     primscale[k * 3 + r], 0.f};
        g_prim[k * 4 + 0] = A;
        g_prim[k * 4 + 1] = Bv;
        g_prim[k * 4 + 2] = Cv;
        g_prim[k * 4 + 3] = Dv;
    }
}

// Exact OBB slab test (cull only). Reads the GLOBAL copy (lane-divergent index).
__device__ __forceinline__ bool obb_test(
    int k,
    float ox, float oy, float oz,
    float dx, float dy, float dz,
    float tmin, float tmax)
{
    float4 A = __ldg(g_prim + k * 4 + 0);
    float4 B = __ldg(g_prim + k * 4 + 1);
    float4 C = __ldg(g_prim + k * 4 + 2);
    float4 D = __ldg(g_prim + k * 4 + 3);
    float rx = ox - C.y, ry = oy - C.z, rz = oz - C.w;
    float lo3[3], ld3[3];
    lo3[0] = (rx * A.x + ry * A.w + rz * B.z) * D.x;
    lo3[1] = (rx * A.y + ry * B.x + rz * B.w) * D.y;
    lo3[2] = (rx * A.z + ry * B.y + rz * C.x) * D.z;
    ld3[0] = (dx * A.x + dy * A.w + dz * B.z) * D.x;
    ld3[1] = (dx * A.y + dy * B.x + dz * B.w) * D.y;
    ld3[2] = (dx * A.z + dy * B.y + dz * C.x) * D.z;
    float t0 = tmin, t1 = tmax;
#pragma unroll
    for (int a = 0; a < 3; a++) {
        float lo = lo3[a], ld = ld3[a];
        if (fabsf(ld) > 1e-12f) {
            float inv = 1.0f / ld;
            float ta = (-1.0f - lo) * inv;
            float tb = ( 1.0f - lo) * inv;
            t0 = fmaxf(t0, fminf(ta, tb));
            t1 = fminf(t1, fmaxf(ta, tb));
        } else if (fabsf(lo) >= 1.0f) {
            return false;
        }
    }
    return t0 <= t1;
}

// One warp per ray; lane owns steps {lane, lane+32}. 8 consecutive rays per block.
// Rows AND column groups assigned center-out (LPT).
// Inner loop: loads for BOTH points issue before any FMA (MLP 8).
__global__ __launch_bounds__(256) void march_kernel(
    const float* __restrict__ raypos,
    const float* __restrict__ raydir,
    const float* __restrict__ tminmax,
    float* __restrict__ out)
{
    int lane = threadIdx.x & 31;
    int warpId = threadIdx.x >> 5;

    // center-out row mapping: i -> 127,128,126,129,...
    int i = blockIdx.x >> 5;          // 0..255
    int rh = i & 1;
    int roff = i >> 1;
    int row = rh ? (128 + roff) : (127 - roff);
    // center-out column-group mapping: j -> 15,16,14,17,...
    int j = blockIdx.x & 31;
    int ch = j & 1;
    int coff = j >> 1;
    int colg = ch ? (16 + coff) : (15 - coff);
    int r = row * WW + colg * 8 + warpId;

    float ox = raypos[r * 3 + 0], oy = raypos[r * 3 + 1], oz = raypos[r * 3 + 2];
    float dx = raydir[r * 3 + 0], dy = raydir[r * 3 + 1], dz = raydir[r * 3 + 2];
    float tmin = tminmax[r * 2 + 0], tmax = tminmax[r * 2 + 1];

    // Cooperative exact-OBB cull: lane tests prims {lane, lane+32}
    bool a0 = obb_test(lane,      ox, oy, oz, dx, dy, dz, tmin, tmax);
    bool a1 = obb_test(lane + 32, ox, oy, oz, dx, dy, dz, tmin, tmax);
    unsigned m0 = __ballot_sync(0xFFFFFFFFu, a0);
    unsigned m1 = __ballot_sync(0xFFFFFFFFu, a1);
    unsigned long long mask = (unsigned long long)m0 |
                              ((unsigned long long)m1 << 32);

    // Two sample points per lane: steps lane and lane+32
    float t0 = fmaf((float)lane + 0.5f,  DTST, tmin);
    float t1 = fmaf((float)lane + 32.5f, DTST, tmin);
    float p0x = fmaf(t0, dx, ox), p0y = fmaf(t0, dy, oy), p0z = fmaf(t0, dz, oz);
    float p1x = fmaf(t1, dx, ox), p1y = fmaf(t1, dy, oy), p1z = fmaf(t1, dz, oz);

    float s0[4] = {0.f, 0.f, 0.f, 0.f};
    float s1[4] = {0.f, 0.f, 0.f, 0.f};

    while (mask) {
        int k = __ffsll(mask) - 1;   // warp-uniform
        mask &= mask - 1;
        float4 A = c_prim[k * 4 + 0];   // LDC, constant port (off L1)
        float4 B = c_prim[k * 4 + 1];
        float4 C = c_prim[k * 4 + 2];
        float4 D = c_prim[k * 4 + 3];

        // --- transforms for both points ---
        float r0x = p0x - C.y, r0y = p0y - C.z, r0z = p0z - C.w;
        float l0x = (r0x * A.x + r0y * A.w + r0z * B.z) * D.x;
        float l0y = (r0x * A.y + r0y * B.x + r0z * B.w) * D.y;
        float l0z = (r0x * A.z + r0y * B.y + r0z * C.x) * D.z;
        bool in0 = fmaxf(fmaxf(fabsf(l0x), fabsf(l0y)), fabsf(l0z)) < 1.0f;

        float r1x = p1x - C.y, r1y = p1y - C.z, r1z = p1z - C.w;
        float l1x = (r1x * A.x + r1y * A.w + r1z * B.z) * D.x;
        float l1y = (r1x * A.y + r1y * B.x + r1z * B.w) * D.y;
        float l1z = (r1x * A.z + r1y * B.y + r1z * C.x) * D.z;
        bool in1 = fmaxf(fmaxf(fabsf(l1x), fabsf(l1y)), fabsf(l1z)) < 1.0f;

        // --- load phase: issue all 8 loads before any FMA ---
        float fx0 = 0.f, fy0 = 0.f, fz0 = 0.f;
        uint4 q00, q01, q10, q11;
        if (in0) {
            float gx = fminf((l0x + 1.0f) * 7.5f, 14.99999f);
            float gy = fminf((l0y + 1.0f) * 7.5f, 14.99999f);
            float gz = fminf((l0z + 1.0f) * 7.5f, 14.99999f);
            int x0 = (int)gx, y0 = (int)gy, z0 = (int)gz;
            fx0 = gx - (float)x0; fy0 = gy - (float)y0; fz0 = gz - (float)z0;
            const uint4* T = g_tmpl + (((k * MV + z0) * MV + y0) * MV + x0);
            q00 = __ldg(T + 0);   q01 = __ldg(T + 16);
            q10 = __ldg(T + 256); q11 = __ldg(T + 272);
        }
        float fx1 = 0.f, fy1 = 0.f, fz1 = 0.f;
        uint4 p00, p01, p10, p11;
        if (in1) {
            float gx = fminf((l1x + 1.0f) * 7.5f, 14.99999f);
            float gy = fminf((l1y + 1.0f) * 7.5f, 14.99999f);
            float gz = fminf((l1z + 1.0f) * 7.5f, 14.99999f);
            int x0 = (int)gx, y0 = (int)gy, z0 = (int)gz;
            fx1 = gx - (float)x0; fy1 = gy - (float)y0; fz1 = gz - (float)z0;
            const uint4* T = g_tmpl + (((k * MV + z0) * MV + y0) * MV + x0);
            p00 = __ldg(T + 0);   p01 = __ldg(T + 16);
            p10 = __ldg(T + 256); p11 = __ldg(T + 272);
        }

#define ACC2(qq, wA, wB, ss)                                              \
    {                                                                     \
        float2 rgA = __half22float2(*reinterpret_cast<const __half2*>(&(qq).x)); \
        float2 baA = __half22float2(*reinterpret_cast<const __half2*>(&(qq).y)); \
        float2 rgB = __half22float2(*reinterpret_cast<const __half2*>(&(qq).z)); \
        float2 baB = __half22float2(*reinterpret_cast<const __half2*>(&(qq).w)); \
        ss[0] = fmaf(rgA.x, (wA), ss[0]); ss[1] = fmaf(rgA.y, (wA), ss[1]); \
        ss[2] = fmaf(baA.x, (wA), ss[2]); ss[3] = fmaf(baA.y, (wA), ss[3]); \
        ss[0] = fmaf(rgB.x, (wB), ss[0]); ss[1] = fmaf(rgB.y, (wB), ss[1]); \
        ss[2] = fmaf(baB.x, (wB), ss[2]); ss[3] = fmaf(baB.y, (wB), ss[3]); \
    }
        // --- math phase point 0 ---
        if (in0) {
            float wz0 = 1.0f - fz0, wy0 = 1.0f - fy0, wx0 = 1.0f - fx0;
            float w000 = wz0 * wy0 * wx0, w001 = wz0 * wy0 * fx0;
            float w010 = wz0 * fy0 * wx0, w011 = wz0 * fy0 * fx0;
            float w100 = fz0 * wy0 * wx0, w101 = fz0 * wy0 * fx0;
            float w110 = fz0 * fy0 * wx0, w111 = fz0 * fy0 * fx0;
            ACC2(q00, w000, w001, s0)
            ACC2(q01, w010, w011, s0)
            ACC2(q10, w100, w101, s0)
            ACC2(q11, w110, w111, s0)
        }
        // --- math phase point 1 ---
        if (in1) {
            float wz0 = 1.0f - fz1, wy0 = 1.0f - fy1, wx0 = 1.0f - fx1;
            float w000 = wz0 * wy0 * wx0, w001 = wz0 * wy0 * fx1;
            float w010 = wz0 * fy1 * wx0, w011 = wz0 * fy1 * fx1;
            float w100 = fz1 * wy0 * wx0, w101 = fz1 * wy0 * fx1;
            float w110 = fz1 * fy1 * wx0, w111 = fz1 * fy1 * fx1;
            ACC2(p00, w000, w001, s1)
            ACC2(p01, w010, w011, s1)
            ACC2(p10, w100, w101, s1)
            ACC2(p11, w110, w111, s1)
        }
#undef ACC2
    }

    // Alpha compositing via prefix sum: alpha_i = min(1, sum_{j<=i} d_j)
    float d0 = (t0 < tmax) ? s0[3] * DTST : 0.f;
    float d1 = (t1 < tmax) ? s1[3] * DTST : 0.f;

    float c0 = d0;
#pragma unroll
    for (int off2 = 1; off2 < 32; off2 <<= 1) {
        float v = __shfl_up_sync(0xFFFFFFFFu, c0, off2);
        if (lane >= off2) c0 += v;
    }
    float tot0 = __shfl_sync(0xFFFFFFFFu, c0, 31);
    float c1 = d1;
#pragma unroll
    for (int off2 = 1; off2 < 32; off2 <<= 1) {
        float v = __shfl_up_sync(0xFFFFFFFFu, c1, off2);
        if (lane >= off2) c1 += v;
    }
    float S0 = c0;            // inclusive prefix at step lane
    float S1 = tot0 + c1;     // inclusive prefix at step lane+32
    float contrib0 = fminf(1.f, S0) - fminf(1.f, S0 - d0);
    float contrib1 = fminf(1.f, S1) - fminf(1.f, S1 - d1);

    float rgbx = s0[0] * contrib0 + s1[0] * contrib1;
    float rgby = s0[1] * contrib0 + s1[1] * contrib1;
    float rgbz = s0[2] * contrib0 + s1[2] * contrib1;

#pragma unroll
    for (int off2 = 16; off2 > 0; off2 >>= 1) {
        rgbx += __shfl_xor_sync(0xFFFFFFFFu, rgbx, off2);
        rgby += __shfl_xor_sync(0xFFFFFFFFu, rgby, off2);
        rgbz += __shfl_xor_sync(0xFFFFFFFFu, rgbz, off2);
    }
    float alphaF = fminf(1.f, __shfl_sync(0xFFFFFFFFu, S1, 31));

    if (lane == 0) {
        const int HWsz = HH * WW;
        out[0 * HWsz + r] = rgbx;
        out[1 * HWsz + r] = rgby;
        out[2 * HWsz + r] = rgbz;
        out[3 * HWsz + r] = alphaF;
        out[4 * HWsz + r] = rgbx;
        out[5 * HWsz + r] = rgby;
        out[6 * HWsz + r] = rgbz;
        out[7 * HWsz + r] = alphaF;
    }
}

extern "C" void kernel_launch(void* const* d_in, const int* in_sizes, int n_in,
                              void* d_out, int out_size) {
    const float* raypos    = (const float*)d_in[0];
    const float* raydir    = (const float*)d_in[1];
    const float* tminmax   = (const float*)d_in[2];
    const float* primpos   = (const float*)d_in[3];
    const float* primrot   = (const float*)d_in[4];
    const float* primscale = (const float*)d_in[5];
    const float* primrgba  = (const float*)d_in[6];
    float* out = (float*)d_out;

    pack_prep_kernel<<<1025, 256>>>(primrgba, primpos, primrot, primscale);

    // Mirror prim params into constant memory (graph-capturable D2D copy).
    void* gp = nullptr;
    cudaGetSymbolAddress(&gp, g_prim);
    cudaMemcpyToSymbolAsync(c_prim, gp, sizeof(float4) * KK * 4, 0,
                            cudaMemcpyDeviceToDevice, 0);

    march_kernel<<<HH * WW / 8, 256>>>(raypos, raydir, tminmax, out);
}